// round 2
// baseline (speedup 1.0000x reference)
#include <cuda_runtime.h>
#include <cuda_bf16.h>

// ---------------------------------------------------------------------------
// SPN neuron: B=32768, F=512, P=256 scope pairs, M=8 mixture components.
//
// out[b] = sum_p logsumexp_m( sum_d logN(x[b,scopes[2p+d]]; mu[p,m,d], sd[p,m,d])
//                             + log(w[p,m]/sum_m w[p,m]) )
//
// Log2-domain quadratic form per (p,m):
//   t_m = A1*x1^2 + B1*x1 + A2*x2^2 + B2*x2 + C     (scaled by log2 e)
//   lse2 = mx + log2( sum_m 2^(t_m - mx) )
//   out[b] = ln(2) * sum_p lse2_p
// Coefficients precomputed once per launch into a __device__ global (40 KB).
// Scopes dtype (int32 vs int64) auto-detected and normalized to int.
// ---------------------------------------------------------------------------

#define LOG2E_F   1.4426950408889634f
#define LN2_F     0.6931471805599453f
#define LOG_2PI_F 1.8378770664093453f

constexpr int PF  = 512;   // features
constexpr int PP  = 256;   // scope pairs
constexpr int PM  = 8;     // mixture components
constexpr int ROWS = 8;    // batch rows staged per chunk

__device__ float g_coef[5 * PM * PP];   // [j in 0..4][m][p], p fastest
__device__ int   g_scopes[PF];          // normalized int32 scopes
__device__ int   g_is64;                // detection result (thread-0 vote)

__device__ __forceinline__ float ex2f(float v) {
    float r; asm("ex2.approx.ftz.f32 %0, %1;" : "=f"(r) : "f"(v)); return r;
}
__device__ __forceinline__ float lg2f(float v) {
    float r; asm("lg2.approx.ftz.f32 %0, %1;" : "=f"(r) : "f"(v)); return r;
}

// ---------------------------------------------------------------------------
// Precompute: 1 block, 256 threads.
//  (a) detect scopes dtype, normalize to g_scopes[512]
//  (b) thread p computes its 8 components' quadratic coefficients
// ---------------------------------------------------------------------------
__global__ void spn_precompute_kernel(const float* __restrict__ mean,
                                      const float* __restrict__ stdv,
                                      const float* __restrict__ wts,
                                      const void* __restrict__ scopes_raw)
{
    const int p = threadIdx.x;
    const int* w32 = (const int*)scopes_raw;

    // --- dtype detection (thread 0): int64 LE values in [0,512) have every
    // odd 32-bit word == 0 across the first 512 words; an int32 permutation
    // of 0..511 cannot (it has exactly one zero total). ---
    if (p == 0) {
        int odd_nonzero = 0;
        for (int i = 1; i < PF; i += 2) odd_nonzero |= (w32[i] != 0);
        g_is64 = !odd_nonzero;
    }
    __syncthreads();
    const int is64 = g_is64;

    // Normalize scopes (512 entries, 256 threads -> 2 each).
    for (int i = p; i < PF; i += 256)
        g_scopes[i] = is64 ? w32[2 * i] : w32[i];

    if (p >= PP) return;

    float wsum = 0.f;
    #pragma unroll
    for (int m = 0; m < PM; m++) wsum += wts[p * PM + m];
    float lwsum = logf(wsum);

    #pragma unroll
    for (int m = 0; m < PM; m++) {
        int base = (p * PM + m) * 2;
        float mu1 = mean[base + 0], mu2 = mean[base + 1];
        float s1  = stdv[base + 0], s2  = stdv[base + 1];
        float i1 = 1.f / (s1 * s1);
        float i2 = 1.f / (s2 * s2);
        float A1 = -0.5f * i1 * LOG2E_F;
        float B1 =  mu1  * i1 * LOG2E_F;
        float A2 = -0.5f * i2 * LOG2E_F;
        float B2 =  mu2  * i2 * LOG2E_F;
        float C  = (-0.5f * (mu1 * mu1 * i1 + mu2 * mu2 * i2)
                    - logf(s1) - logf(s2) - LOG_2PI_F
                    + logf(wts[p * PM + m]) - lwsum) * LOG2E_F;
        g_coef[(0 * PM + m) * PP + p] = A1;
        g_coef[(1 * PM + m) * PP + p] = B1;
        g_coef[(2 * PM + m) * PP + p] = A2;
        g_coef[(3 * PM + m) * PP + p] = B2;
        g_coef[(4 * PM + m) * PP + p] = C;
    }
}

// ---------------------------------------------------------------------------
// Main kernel: blockDim = 256 (thread == scope pair p, coefficients in regs).
// Each block processes rows_per_block batch rows in chunks of ROWS:
//   - coalesced float4 stage of ROWS rows into smem
//   - per-row: gather 2 features, quadratic form for 8 components, logsumexp
//   - per-row cross-thread reduction: warp shuffle + 8-warp finalize
// ---------------------------------------------------------------------------
__global__ __launch_bounds__(256, 2)
void spn_main_kernel(const float* __restrict__ x,
                     float* __restrict__ out,
                     int rows_per_block)
{
    __shared__ float sx[ROWS][PF];
    __shared__ float sred[8][ROWS];

    const int tid  = threadIdx.x;
    const int p    = tid;
    const int lane = tid & 31;
    const int warp = tid >> 5;

    // Coefficients -> registers (coalesced: p is fastest dim of g_coef)
    float A1[PM], B1[PM], A2[PM], B2[PM], C[PM];
    #pragma unroll
    for (int m = 0; m < PM; m++) {
        A1[m] = g_coef[(0 * PM + m) * PP + p];
        B1[m] = g_coef[(1 * PM + m) * PP + p];
        A2[m] = g_coef[(2 * PM + m) * PP + p];
        B2[m] = g_coef[(3 * PM + m) * PP + p];
        C [m] = g_coef[(4 * PM + m) * PP + p];
    }
    const int s0 = g_scopes[2 * p + 0] & (PF - 1);   // clamp defensively
    const int s1 = g_scopes[2 * p + 1] & (PF - 1);

    const int row0 = blockIdx.x * rows_per_block;

    for (int base = row0; base < row0 + rows_per_block; base += ROWS) {
        // Stage ROWS rows, coalesced float4 (ROWS*PF/4 = 1024 float4, 4/thread)
        const float4* gx = reinterpret_cast<const float4*>(x + (size_t)base * PF);
        float4* s4 = reinterpret_cast<float4*>(&sx[0][0]);
        #pragma unroll
        for (int k = 0; k < (ROWS * PF / 4) / 256; k++)
            s4[tid + k * 256] = gx[tid + k * 256];
        __syncthreads();

        float acc[ROWS];
        #pragma unroll
        for (int r = 0; r < ROWS; r++) {
            float x1 = sx[r][s0];
            float x2 = sx[r][s1];
            float x1s = x1 * x1;
            float x2s = x2 * x2;

            float t[PM];
            #pragma unroll
            for (int m = 0; m < PM; m++) {
                float v = fmaf(B2[m], x2, C[m]);
                v = fmaf(A2[m], x2s, v);
                v = fmaf(B1[m], x1, v);
                v = fmaf(A1[m], x1s, v);
                t[m] = v;
            }
            float mx = t[0];
            #pragma unroll
            for (int m = 1; m < PM; m++) mx = fmaxf(mx, t[m]);
            float s = 0.f;
            #pragma unroll
            for (int m = 0; m < PM; m++) s += ex2f(t[m] - mx);
            acc[r] = mx + lg2f(s);
        }

        // Reduce 256 per-pair contributions -> 1 value per row
        #pragma unroll
        for (int r = 0; r < ROWS; r++) {
            float v = acc[r];
            #pragma unroll
            for (int off = 16; off; off >>= 1)
                v += __shfl_xor_sync(0xffffffffu, v, off);
            if (lane == 0) sred[warp][r] = v;
        }
        __syncthreads();

        if (tid < ROWS) {
            float s = 0.f;
            #pragma unroll
            for (int w = 0; w < 8; w++) s += sred[w][tid];
            out[base + tid] = s * LN2_F;
        }
        __syncthreads();
    }
}

// ---------------------------------------------------------------------------
// Launch. Inputs (metadata order): x f32[32768*512], mean f32[256*8*2],
// std f32[256*8*2], weights f32[256*8], scopes int{32,64}[512].
// Output f32[32768].
// ---------------------------------------------------------------------------
extern "C" void kernel_launch(void* const* d_in, const int* in_sizes, int n_in,
                              void* d_out, int out_size)
{
    const float* x      = (const float*)d_in[0];
    const float* mean   = (const float*)d_in[1];
    const float* stdv   = (const float*)d_in[2];
    const float* wts    = (const float*)d_in[3];
    const void*  scopes = d_in[4];
    float*       out    = (float*)d_out;

    const int B = in_sizes[0] / PF;   // 32768

    spn_precompute_kernel<<<1, 256>>>(mean, stdv, wts, scopes);

    // 1024 blocks * 32 rows = 32768; 4 chunks of ROWS=8 per block.
    int blocks = 1024;
    int rpb = B / blocks;             // 32
    if (rpb * blocks != B || (rpb % ROWS) != 0) {
        blocks = (B + ROWS - 1) / ROWS;
        rpb = ROWS;
    }
    spn_main_kernel<<<blocks, 256>>>(x, out, rpb);
}

// round 4
// speedup vs baseline: 1.0961x; 1.0961x over previous
#include <cuda_runtime.h>
#include <cuda_bf16.h>
#include <cstdint>

// ---------------------------------------------------------------------------
// SPN neuron: B=32768, F=512, P=256 scope pairs, M=8 mixture components.
//
// Log2-domain quadratic form per (p,m):
//   t_m = A1*x1^2 + B1*x1 + A2*x2^2 + B2*x2 + C     (scaled by log2 e)
//   lse2 = mx + log2( sum_m 2^(t_m - mx) )
//   out[b] = ln(2) * sum_p lse2_p
//
// R3: (R2 design, compile-fixed) double-buffered cp.async pipeline +
// persistent grid-stride blocks to hide HBM latency behind the MUFU/FMA
// compute floor (~20us).
// ---------------------------------------------------------------------------

#define LOG2E_F   1.4426950408889634f
#define LN2_F     0.6931471805599453f
#define LOG_2PI_F 1.8378770664093453f

constexpr int PF   = 512;   // features
constexpr int PP   = 256;   // scope pairs
constexpr int PM   = 8;     // mixture components
constexpr int ROWS = 8;     // batch rows per chunk

__device__ float g_coef[5 * PM * PP];   // [j in 0..4][m][p], p fastest
__device__ int   g_scopes[PF];          // normalized int32 scopes
__device__ int   g_is64;

__device__ __forceinline__ float ex2f(float v) {
    float r; asm("ex2.approx.ftz.f32 %0, %1;" : "=f"(r) : "f"(v)); return r;
}
__device__ __forceinline__ float lg2f(float v) {
    float r; asm("lg2.approx.ftz.f32 %0, %1;" : "=f"(r) : "f"(v)); return r;
}
__device__ __forceinline__ void cp16(uint32_t smem_dst, const void* gmem_src) {
    asm volatile("cp.async.cg.shared.global [%0], [%1], 16;\n"
                 :: "r"(smem_dst), "l"(gmem_src));
}
__device__ __forceinline__ void cp_commit() {
    asm volatile("cp.async.commit_group;\n" ::: "memory");
}
template <int N>
__device__ __forceinline__ void cp_wait() {
    asm volatile("cp.async.wait_group %0;\n" :: "n"(N) : "memory");
}

// ---------------------------------------------------------------------------
// Precompute: 1 block, 256 threads.
// ---------------------------------------------------------------------------
__global__ void spn_precompute_kernel(const float* __restrict__ mean,
                                      const float* __restrict__ stdv,
                                      const float* __restrict__ wts,
                                      const void* __restrict__ scopes_raw)
{
    const int p = threadIdx.x;
    const int* w32 = (const int*)scopes_raw;

    // dtype detection: int64 LE values in [0,512) have every odd 32-bit word
    // zero across the first 512 words; an int32 permutation of 0..511 cannot.
    if (p == 0) {
        int odd_nonzero = 0;
        for (int i = 1; i < PF; i += 2) odd_nonzero |= (w32[i] != 0);
        g_is64 = !odd_nonzero;
    }
    __syncthreads();
    const int is64 = g_is64;
    for (int i = p; i < PF; i += 256)
        g_scopes[i] = is64 ? w32[2 * i] : w32[i];

    if (p >= PP) return;

    float wsum = 0.f;
    #pragma unroll
    for (int m = 0; m < PM; m++) wsum += wts[p * PM + m];
    float lwsum = logf(wsum);

    #pragma unroll
    for (int m = 0; m < PM; m++) {
        int base = (p * PM + m) * 2;
        float mu1 = mean[base + 0], mu2 = mean[base + 1];
        float s1  = stdv[base + 0], s2  = stdv[base + 1];
        float i1 = 1.f / (s1 * s1);
        float i2 = 1.f / (s2 * s2);
        float A1 = -0.5f * i1 * LOG2E_F;
        float B1 =  mu1  * i1 * LOG2E_F;
        float A2 = -0.5f * i2 * LOG2E_F;
        float B2 =  mu2  * i2 * LOG2E_F;
        float C  = (-0.5f * (mu1 * mu1 * i1 + mu2 * mu2 * i2)
                    - logf(s1) - logf(s2) - LOG_2PI_F
                    + logf(wts[p * PM + m]) - lwsum) * LOG2E_F;
        g_coef[(0 * PM + m) * PP + p] = A1;
        g_coef[(1 * PM + m) * PP + p] = B1;
        g_coef[(2 * PM + m) * PP + p] = A2;
        g_coef[(3 * PM + m) * PP + p] = B2;
        g_coef[(4 * PM + m) * PP + p] = C;
    }
}

// ---------------------------------------------------------------------------
// Main kernel: blockDim = 256 (thread == scope pair p, coefficients in regs).
// Persistent grid-stride over 8-row chunks; double-buffered cp.async staging.
// ---------------------------------------------------------------------------
__global__ __launch_bounds__(256, 2)
void spn_main_kernel(const float* __restrict__ x,
                     float* __restrict__ out,
                     int nchunks)
{
    __shared__ float sx[2][ROWS][PF];
    __shared__ float sred[8][ROWS];

    const int tid  = threadIdx.x;
    const int p    = tid;
    const int lane = tid & 31;
    const int warp = tid >> 5;

    // Coefficients -> registers (coalesced: p fastest dim of g_coef)
    float A1[PM], B1[PM], A2[PM], B2[PM], C[PM];
    #pragma unroll
    for (int m = 0; m < PM; m++) {
        A1[m] = g_coef[(0 * PM + m) * PP + p];
        B1[m] = g_coef[(1 * PM + m) * PP + p];
        A2[m] = g_coef[(2 * PM + m) * PP + p];
        B2[m] = g_coef[(3 * PM + m) * PP + p];
        C [m] = g_coef[(4 * PM + m) * PP + p];
    }
    const int s0 = g_scopes[2 * p + 0] & (PF - 1);
    const int s1 = g_scopes[2 * p + 1] & (PF - 1);

    const int stride = gridDim.x;
    const uint32_t sbase = (uint32_t)__cvta_generic_to_shared(&sx[0][0][0]);

    // Prologue: stage first chunk into buffer 0.
    int c = blockIdx.x;
    if (c < nchunks) {
        const char* src = (const char*)(x + (size_t)c * ROWS * PF);
        #pragma unroll
        for (int k = 0; k < 4; k++)
            cp16(sbase + (tid + k * 256) * 16, src + (tid + k * 256) * 16);
    }
    cp_commit();

    int buf = 0;
    for (; c < nchunks; c += stride, buf ^= 1) {
        // Issue next chunk into the other buffer (empty group if none).
        int cn = c + stride;
        if (cn < nchunks) {
            const char* src = (const char*)(x + (size_t)cn * ROWS * PF);
            uint32_t dst = sbase + (uint32_t)(buf ^ 1) * (ROWS * PF * 4);
            #pragma unroll
            for (int k = 0; k < 4; k++)
                cp16(dst + (tid + k * 256) * 16, src + (tid + k * 256) * 16);
        }
        cp_commit();
        cp_wait<1>();          // current chunk's group has landed
        __syncthreads();       // visible to all; sred from prev iter consumed

        float acc[ROWS];
        #pragma unroll
        for (int r = 0; r < ROWS; r++) {
            float x1 = sx[buf][r][s0];
            float x2 = sx[buf][r][s1];
            float x1s = x1 * x1;
            float x2s = x2 * x2;

            float t[PM];
            #pragma unroll
            for (int m = 0; m < PM; m++) {
                float v = fmaf(B2[m], x2, C[m]);
                v = fmaf(A2[m], x2s, v);
                v = fmaf(B1[m], x1, v);
                v = fmaf(A1[m], x1s, v);
                t[m] = v;
            }
            // max tree (depth 3)
            float m01 = fmaxf(t[0], t[1]), m23 = fmaxf(t[2], t[3]);
            float m45 = fmaxf(t[4], t[5]), m67 = fmaxf(t[6], t[7]);
            float m03 = fmaxf(m01, m23),   m47 = fmaxf(m45, m67);
            float mx  = fmaxf(m03, m47);
            float s = 0.f;
            #pragma unroll
            for (int m = 0; m < PM; m++) s += ex2f(t[m] - mx);
            acc[r] = mx + lg2f(s);
        }

        // Reduce 256 per-pair contributions -> 1 value per row
        #pragma unroll
        for (int r = 0; r < ROWS; r++) {
            float v = acc[r];
            #pragma unroll
            for (int off = 16; off; off >>= 1)
                v += __shfl_xor_sync(0xffffffffu, v, off);
            if (lane == 0) sred[warp][r] = v;
        }
        __syncthreads();

        if (tid < ROWS) {
            float s = 0.f;
            #pragma unroll
            for (int w = 0; w < 8; w++) s += sred[w][tid];
            out[c * ROWS + tid] = s * LN2_F;
        }
        // No trailing barrier: next iter's top barrier (after cp_wait) orders
        // this iter's sred reads against next iter's sred writes, and the
        // cp.async issued at next-iter top targets the buffer whose last
        // reads were sealed by this iteration's mid barrier.
    }
}

// ---------------------------------------------------------------------------
// Launch. Inputs: x f32[32768*512], mean f32[256*8*2], std f32[256*8*2],
// weights f32[256*8], scopes int{32,64}[512]. Output f32[32768].
// ---------------------------------------------------------------------------
extern "C" void kernel_launch(void* const* d_in, const int* in_sizes, int n_in,
                              void* d_out, int out_size)
{
    const float* x      = (const float*)d_in[0];
    const float* mean   = (const float*)d_in[1];
    const float* stdv   = (const float*)d_in[2];
    const float* wts    = (const float*)d_in[3];
    const void*  scopes = d_in[4];
    float*       out    = (float*)d_out;

    const int B = in_sizes[0] / PF;          // 32768
    const int nchunks = B / ROWS;            // 4096 (B % ROWS == 0 here)

    spn_precompute_kernel<<<1, 256>>>(mean, stdv, wts, scopes);

    int blocks = 1184;                       // ~8 per SM; persistent grid-stride
    if (blocks > nchunks) blocks = nchunks;
    spn_main_kernel<<<blocks, 256>>>(x, out, nchunks);
}